// round 8
// baseline (speedup 1.0000x reference)
#include <cuda_runtime.h>

#define T_STEPS 730
#define N_GRID  10000
#define LENF    15
#define NEARZERO 1e-5f
#define BLK   32            // ONE WARP per block (2 threads per cell)
#define GPB   16            // grid cells per block; 625 * 16 = 10000 exactly
#define CHUNK 7             // timesteps per stage
#define NBUF  4             // cp.async ring depth
#define NCHUNKS 105         // ceil(730/7); chunk 104 has 2 live steps

// Shared staging: x padded to 4 floats/cell so (P,Ta,PE) is one LDS.128.
struct __align__(16) Smem {
    float sx[NBUF][CHUNK][GPB * 4];   // P, Ta, PET, pad
    float sd[NBUF][CHUNK][GPB * 4];   // beta_m0, beta_m1, betaet_m0, betaet_m1
};

__device__ __forceinline__ void cp16(void* dst_smem, const void* src) {
    unsigned d = (unsigned)__cvta_generic_to_shared(dst_smem);
    asm volatile("cp.async.ca.shared.global [%0], [%1], 16;\n" :: "r"(d), "l"(src));
}
__device__ __forceinline__ void cp4(void* dst_smem, const void* src) {
    unsigned d = (unsigned)__cvta_generic_to_shared(dst_smem);
    asm volatile("cp.async.ca.shared.global [%0], [%1], 4;\n" :: "r"(d), "l"(src));
}
__device__ __forceinline__ float lg2a(float x) {
    float r; asm("lg2.approx.f32 %0, %1;" : "=f"(r) : "f"(x)); return r;
}
__device__ __forceinline__ float ex2a(float x) {
    float r; asm("ex2.approx.f32 %0, %1;" : "=f"(r) : "f"(x)); return r;
}

// Stage CHUNK timesteps of chunk `ch` into ring buffer ch&3 (addresses clamped).
__device__ __forceinline__ void stage(
    Smem& s, int ch, int gb,
    const float* __restrict__ x_phy, const float* __restrict__ pdy, int lane)
{
    const int buf = ch & 3;
    const int t0  = ch * CHUNK;
    // x: 7*16*3 = 336 scalar floats, padded into stride-4 slots
    const int limx = T_STEPS * N_GRID * 3 - 1;
    #pragma unroll
    for (int v = 0; v < 11; ++v) {
        const int i = lane + v * BLK;
        if (v < 10 || i < CHUNK * GPB * 3) {
            const int st = i / 48, r = i % 48;
            const int cell = r / 3, comp = r % 3;
            int idx = (t0 + st) * (N_GRID * 3) + (gb + cell) * 3 + comp;
            idx = (idx > limx) ? limx : idx;
            cp4(&s.sx[buf][st][cell * 4 + comp], x_phy + idx);
        }
    }
    // d: 7*16*4 = 448 floats = 112 16B vectors
    const int limd = T_STEPS * N_GRID * 4 - 4;
    #pragma unroll
    for (int v = 0; v < 4; ++v) {
        const int i = lane + v * BLK;
        if (i < CHUNK * GPB) {           // 112
            const int st = i >> 4, o = i & 15;
            int idx = (t0 + st) * (N_GRID * 4) + gb * 4 + o * 4;
            idx = (idx > limd) ? limd : idx;
            cp16(&s.sd[buf][st][o * 4], pdy + idx);
        }
    }
}

// Per-component HBV parameters (hoisted/precombined)
struct Chain {
    float parFC, parK0, parK1, parK2, parPERC, parUZL, parTT,
          parCFMAX, parCWH, parC;
    float invFC, invLPFC, crf, gwcap, cfmaxTT, crfTT;
};

// One HBV step + per-component 15-tap routing (weights pre-scaled by 0.5).
// RP = t mod 14 (compile-time): static ring indexing. Slot in buffer = RP%7.
template<int RP>
__device__ __forceinline__ void step_body(
    const Chain& S, float& snowpack, float& meltwater, float& sm, float& suz,
    float& slz, float& lsm,
    const float (&w)[LENF], float (&qh)[14], int m,
    const float* __restrict__ px, const float* __restrict__ pd,
    float* __restrict__ outp)
{
    constexpr int SL = RP % 7;
    const float4 xv = *reinterpret_cast<const float4*>(px + SL * (GPB * 4));
    const float4 dv = *reinterpret_cast<const float4*>(pd + SL * (GPB * 4));
    const float P  = xv.x;
    const float Ta = xv.y;
    const float PE = xv.z;
    const float beta   = (m ? dv.y : dv.x) * 5.0f + 1.0f;   // [1,6]
    const float betaet = (m ? dv.w : dv.z) * 4.7f + 0.3f;   // [0.3,5]

    // swet from carried lsm = lg2(sm_prev * invFC)
    const float swet = __saturatef(ex2a(beta * lsm));

    // --- snow bucket ---
    const bool wet = (Ta >= S.parTT);
    const float rain = wet ? P : 0.0f;
    const float snow = wet ? 0.0f : P;
    const float melt0 = fmaxf(fmaf(S.parCFMAX, Ta, -S.cfmaxTT), 0.0f);
    const float refr0 = fmaxf(fmaf(-S.crf, Ta, S.crfTT), 0.0f);
    float sp1 = snowpack + snow;
    const float melt = fminf(melt0, sp1);
    float mw1 = meltwater + melt;
    sp1 -= melt;
    const float refr = fminf(refr0, mw1);
    sp1 += refr;
    mw1 -= refr;
    const float tosoil = fmaxf(fmaf(-S.parCWH, sp1, mw1), 0.0f);
    snowpack = sp1;
    meltwater = mw1 - tosoil;

    // --- soil bucket ---
    const float rpt = rain + tosoil;
    const float recharge = rpt * swet;
    const float sm1 = sm + (rpt - recharge);
    const float sm2 = fminf(sm1, S.parFC);
    const float excess = sm1 - sm2;
    const float efb = __saturatef(sm2 * S.invLPFC);
    const float ef  = ex2a(betaet * lg2a(efb));
    const float sm3 = fmaxf(fmaf(-PE, ef, sm2), NEARZERO);
    const float cslz = S.parC * slz;
    const float f1  = 1.0f - __saturatef(sm3 * S.invFC);
    const float cap = fminf(cslz * f1, slz);
    const float sm4 = fmaxf(sm3 + cap, NEARZERO);
    float slz2 = fmaxf(slz - cap, NEARZERO);
    sm = sm4;
    lsm = lg2a(sm4 * S.invFC);          // tail: feeds next step's swet

    // --- groundwater buckets ---
    const float suz1 = suz + (recharge + excess);
    const float perc = fminf(suz1, S.parPERC);
    const float suz2 = suz1 - perc;
    const float q0 = S.parK0 * fmaxf(suz2 - S.parUZL, 0.0f);
    const float suz3 = suz2 - q0;
    const float q1 = S.parK1 * suz3;
    suz = suz3 - q1;
    const float slzp = slz2 + perc;
    const float slza = fmaxf(slzp - S.gwcap, 0.0f);
    const float q2 = S.parK2 * slza;
    slz = slza - q2;
    const float qt = (q0 + q1) + q2;

    // --- routing: own component, 15 taps, weights pre-scaled by 0.5;
    //     flow = own partial + sibling partial (one shfl).
    float a0 = w[0] * qt;
    float a1 = w[5] * qh[(RP + 14 - 5) % 14];
    float a2 = w[10] * qh[(RP + 14 - 10) % 14];
    #pragma unroll
    for (int k = 1; k <= 4; ++k)  a0 = fmaf(w[k], qh[(RP + 14 - k) % 14], a0);
    #pragma unroll
    for (int k = 6; k <= 9; ++k)  a1 = fmaf(w[k], qh[(RP + 14 - k) % 14], a1);
    #pragma unroll
    for (int k = 11; k <= 14; ++k) a2 = fmaf(w[k], qh[(RP + 14 - k) % 14], a2);
    qh[RP] = qt;
    const float partial = (a0 + a1) + a2;
    const float flow = partial + __shfl_xor_sync(0xffffffffu, partial, 1);

    if (m == 0) outp[SL * N_GRID] = flow;
}

__global__ void __launch_bounds__(BLK) hbv_fused(
    const float* __restrict__ x_phy,   // [T, G, 3]
    const float* __restrict__ ac_all,  // [G]
    const float* __restrict__ pdy,     // [T, G, 2, 2]
    const float* __restrict__ pstat,   // [G, 30]
    float* __restrict__ out)           // [T, G]
{
    __shared__ Smem smem;

    const int gb   = blockIdx.x * GPB;
    const int lane = threadIdx.x;
    const int lg   = lane >> 1;
    const int m    = lane & 1;
    const int g    = gb + lg;          // always < N_GRID (625*16 = 10000)

    // ---------- static params ----------
    const float* ps = pstat + g * 30;
    const float Ac = ac_all[g];
    Chain S;
    S.parFC    = ps[0*2+m]  * 950.0f  + 50.0f;
    S.parK0    = ps[1*2+m]  * 0.85f   + 0.05f;
    S.parK1    = ps[2*2+m]  * 0.49f   + 0.01f;
    S.parK2    = ps[3*2+m]  * 0.199f  + 0.001f;
    const float parLP = ps[4*2+m] * 0.8f + 0.2f;
    S.parPERC  = ps[5*2+m]  * 10.0f;
    S.parUZL   = ps[6*2+m]  * 100.0f;
    S.parTT    = ps[7*2+m]  * 5.0f    - 2.5f;
    S.parCFMAX = ps[8*2+m]  * 9.5f    + 0.5f;
    const float parCFR = ps[9*2+m] * 0.1f;
    S.parCWH   = ps[10*2+m] * 0.2f;
    S.parC     = ps[11*2+m];
    const float parRT = ps[12*2+m] * 20.0f;
    const float parAC = ps[13*2+m] * 2500.0f;
    S.invFC   = 1.0f / S.parFC;
    S.invLPFC = 1.0f / (parLP * S.parFC);
    S.crf     = parCFR * S.parCFMAX;
    S.gwcap   = parRT * fminf(fmaxf(1.0f - Ac / (parAC + NEARZERO), 0.0f), 1.0f);
    S.cfmaxTT = S.parCFMAX * S.parTT;
    S.crfTT   = S.crf * S.parTT;

    // ---------- normalized gamma-UH weights (pre-scaled by 0.5) ----------
    const float a_r  = fmaxf(ps[28] * 2.9f, 0.0f) + 0.1f;
    const float th_r = fmaxf(ps[29] * 6.5f, 0.0f) + 0.5f;
    const float am1  = a_r - 1.0f;
    const float ivtl = 1.4426950408889634f / th_r;
    const float LOG2TK[LENF] = {
        -1.0f,        0.5849625f, 1.3219281f, 1.8073549f, 2.1699250f,
         2.4594316f,  2.7004397f, 2.9068906f, 3.0874628f, 3.2479275f,
         3.3923174f,  3.5235620f, 3.6438562f, 3.7548875f, 3.8579810f };
    float w[LENF];
    float wsum = 0.0f;
    #pragma unroll
    for (int k = 0; k < LENF; ++k) {
        const float tk = (float)k + 0.5f;
        w[k] = ex2a(am1 * LOG2TK[k] - tk * ivtl);
        wsum += w[k];
    }
    const float ivw = 0.5f / wsum;
    #pragma unroll
    for (int k = 0; k < LENF; ++k) w[k] *= ivw;

    // ---------- state ----------
    float snowpack = 1e-3f, meltwater = 1e-3f, sm = 1e-3f, suz = 1e-3f, slz = 1e-3f;
    float lsm = lg2a(1e-3f * S.invFC);
    float qh[14];
    #pragma unroll
    for (int k = 0; k < 14; ++k) qh[k] = 0.0f;

    // shared read base pointers (buffer 0)
    const float* px0 = &smem.sx[0][0][lg * 4];
    const float* pd0 = &smem.sd[0][0][lg * 4];
    const int bstride = CHUNK * GPB * 4;   // floats per ring buffer

    // ---------- prologue: stage chunks 0,1,2 ----------
    stage(smem, 0, gb, x_phy, pdy, lane);
    asm volatile("cp.async.commit_group;\n");
    stage(smem, 1, gb, x_phy, pdy, lane);
    asm volatile("cp.async.commit_group;\n");
    stage(smem, 2, gb, x_phy, pdy, lane);
    asm volatile("cp.async.commit_group;\n");

    #define STEPS7(B) \
        step_body<B+0>(S, snowpack, meltwater, sm, suz, slz, lsm, w, qh, m, px, pd, outp); \
        step_body<B+1>(S, snowpack, meltwater, sm, suz, slz, lsm, w, qh, m, px, pd, outp); \
        step_body<B+2>(S, snowpack, meltwater, sm, suz, slz, lsm, w, qh, m, px, pd, outp); \
        step_body<B+3>(S, snowpack, meltwater, sm, suz, slz, lsm, w, qh, m, px, pd, outp); \
        step_body<B+4>(S, snowpack, meltwater, sm, suz, slz, lsm, w, qh, m, px, pd, outp); \
        step_body<B+5>(S, snowpack, meltwater, sm, suz, slz, lsm, w, qh, m, px, pd, outp); \
        step_body<B+6>(S, snowpack, meltwater, sm, suz, slz, lsm, w, qh, m, px, pd, outp);

    // one consume-chunk: buffer BUF (compile-time), ring phase PH (0 or 7)
    #define CONSUME(CH, BUF, PH)                                              \
    {                                                                         \
        asm volatile("cp.async.wait_group 2;\n");                             \
        __syncwarp();                                                         \
        const float* px = px0 + (BUF) * bstride;                              \
        const float* pd = pd0 + (BUF) * bstride;                              \
        float* outp = out + (CH) * (CHUNK * N_GRID) + g;                      \
        STEPS7(PH)                                                            \
        const int nch = (CH) + 3;                                             \
        if (nch < NCHUNKS) stage(smem, nch, gb, x_phy, pdy, lane);            \
        asm volatile("cp.async.commit_group;\n");                             \
    }

    // ---------- main loop: 26 iterations x 4 chunks = 104 chunks (t=0..727) ----------
    for (int p = 0; p < 26; ++p) {
        const int ch = p * 4;
        CONSUME(ch + 0, 0, 0)
        CONSUME(ch + 1, 1, 7)
        CONSUME(ch + 2, 2, 0)
        CONSUME(ch + 3, 3, 7)
    }

    // ---------- epilogue: chunk 104 (buf 0, phase 0), live steps 728..729 ----------
    asm volatile("cp.async.wait_group 0;\n");
    __syncwarp();
    {
        const float* px = px0;
        const float* pd = pd0;
        float* outp = out + 104 * (CHUNK * N_GRID) + g;
        step_body<0>(S, snowpack, meltwater, sm, suz, slz, lsm, w, qh, m, px, pd, outp);
        step_body<1>(S, snowpack, meltwater, sm, suz, slz, lsm, w, qh, m, px, pd, outp);
    }
    #undef CONSUME
    #undef STEPS7
}

// ---------------------------------------------------------------------------
extern "C" void kernel_launch(void* const* d_in, const int* in_sizes, int n_in,
                              void* d_out, int out_size)
{
    const float* x_phy = (const float*)d_in[0];   // [730,10000,3]
    const float* ac    = (const float*)d_in[1];   // [10000]
    // d_in[2] = elev_all (unused)
    const float* pdy   = (const float*)d_in[3];   // [730,10000,4]
    const float* pstat = (const float*)d_in[4];   // [10000,30]
    float* out = (float*)d_out;                   // [730,10000,1]

    hbv_fused<<<2 * N_GRID / BLK, BLK>>>(x_phy, ac, pdy, pstat, out);
}

// round 9
// speedup vs baseline: 1.0129x; 1.0129x over previous
#include <cuda_runtime.h>

#define T_STEPS 730
#define N_GRID  10000
#define LENF    15
#define NEARZERO 1e-5f
#define BLK   192           // 6 warps per block -> grid of 105 blocks (<=148 SMs)
#define GPB   96            // grid cells per block (2 threads per cell)
#define CHUNK 7             // timesteps per stage
#define NCHUNKS 105         // ceil(730/7); chunk 104 has 2 live steps

// Shared staging: [buf][step][data]
struct __align__(16) Smem {
    float sx[2][CHUNK][GPB * 3];   // P, Ta, PET per cell
    float sd[2][CHUNK][GPB * 4];   // parBETA(m0,m1), parBETAET(m0,m1)
};

__device__ __forceinline__ void cp16(void* dst_smem, const void* src) {
    unsigned d = (unsigned)__cvta_generic_to_shared(dst_smem);
    asm volatile("cp.async.ca.shared.global [%0], [%1], 16;\n" :: "r"(d), "l"(src));
}
__device__ __forceinline__ float lg2a(float x) {
    float r; asm("lg2.approx.f32 %0, %1;" : "=f"(r) : "f"(x)); return r;
}
__device__ __forceinline__ float ex2a(float x) {
    float r; asm("ex2.approx.f32 %0, %1;" : "=f"(r) : "f"(x)); return r;
}

// Stage CHUNK timesteps of chunk `ch` into buffer ch&1 (addresses clamped).
// x: 7 * (96*3/4) = 504 16B-vecs; d: 7 * 96 = 672 16B-vecs; 192 threads.
__device__ __forceinline__ void stage(
    Smem& s, int ch, int gb,
    const float* __restrict__ x_phy, const float* __restrict__ pdy, int c)
{
    const int buf = ch & 1;
    const int t0  = ch * CHUNK;
    const int limx = T_STEPS * N_GRID * 3 - 4;
    #pragma unroll
    for (int v = 0; v < 3; ++v) {
        const int i = c + v * BLK;
        if (i < CHUNK * 72) {                    // 504
            const int st = i / 72, o = i % 72;
            int idx = (t0 + st) * (N_GRID * 3) + gb * 3 + o * 4;
            idx = (idx > limx) ? limx : idx;
            cp16(&s.sx[buf][st][o * 4], x_phy + idx);
        }
    }
    const int limd = T_STEPS * N_GRID * 4 - 4;
    #pragma unroll
    for (int v = 0; v < 4; ++v) {
        const int i = c + v * BLK;
        if (i < CHUNK * 96) {                    // 672
            const int st = i / 96, o = i % 96;
            int idx = (t0 + st) * (N_GRID * 4) + gb * 4 + o * 4;
            idx = (idx > limd) ? limd : idx;
            cp16(&s.sd[buf][st][o * 4], pdy + idx);
        }
    }
}

// Per-component HBV parameters (hoisted/precombined)
struct Chain {
    float parFC, parK0, parK1, parK2, parPERC, parUZL, parTT,
          parCFMAX, parCWH, parC;
    float invFC, invLPFC, crf, gwcap, cfmaxTT, crfTT;
};

// One HBV step + per-component 15-tap routing (weights pre-scaled by 0.5).
// RP = t mod 14 (compile-time): static ring indexing. Slot in buffer = RP%7.
template<int RP>
__device__ __forceinline__ void step_body(
    const Chain& S, float& snowpack, float& meltwater, float& sm, float& suz,
    float& slz, float& lsm,
    const float (&w)[LENF], float (&qh)[14],
    const float* __restrict__ px, const float* __restrict__ pd0,
    const float* __restrict__ pd1,
    bool store_ok, float* __restrict__ outp)
{
    constexpr int SL = RP % 7;
    const float P  = px[SL * (GPB * 3) + 0];
    const float Ta = px[SL * (GPB * 3) + 1];
    const float PE = px[SL * (GPB * 3) + 2];
    const float beta   = pd0[SL * (GPB * 4)] * 5.0f + 1.0f;   // [1,6]
    const float betaet = pd1[SL * (GPB * 4)] * 4.7f + 0.3f;   // [0.3,5]

    // swet from carried lsm = lg2(sm_prev * invFC)
    const float swet = __saturatef(ex2a(beta * lsm));

    // --- snow bucket ---
    const bool wet = (Ta >= S.parTT);
    const float rain = wet ? P : 0.0f;
    const float snow = wet ? 0.0f : P;
    const float melt0 = fmaxf(fmaf(S.parCFMAX, Ta, -S.cfmaxTT), 0.0f);
    const float refr0 = fmaxf(fmaf(-S.crf, Ta, S.crfTT), 0.0f);
    float sp1 = snowpack + snow;
    const float melt = fminf(melt0, sp1);
    float mw1 = meltwater + melt;
    sp1 -= melt;
    const float refr = fminf(refr0, mw1);
    sp1 += refr;
    mw1 -= refr;
    const float tosoil = fmaxf(fmaf(-S.parCWH, sp1, mw1), 0.0f);
    snowpack = sp1;
    meltwater = mw1 - tosoil;

    // --- soil bucket ---
    const float rpt = rain + tosoil;
    const float recharge = rpt * swet;
    const float sm1 = sm + (rpt - recharge);
    const float sm2 = fminf(sm1, S.parFC);
    const float excess = sm1 - sm2;
    const float efb = __saturatef(sm2 * S.invLPFC);
    const float ef  = ex2a(betaet * lg2a(efb));
    const float sm3 = fmaxf(fmaf(-PE, ef, sm2), NEARZERO);
    const float cslz = S.parC * slz;
    const float f1  = 1.0f - __saturatef(sm3 * S.invFC);
    const float cap = fminf(cslz * f1, slz);
    const float sm4 = fmaxf(sm3 + cap, NEARZERO);
    float slz2 = fmaxf(slz - cap, NEARZERO);
    sm = sm4;
    lsm = lg2a(sm4 * S.invFC);          // tail: feeds next step's swet

    // --- groundwater buckets ---
    const float suz1 = suz + (recharge + excess);
    const float perc = fminf(suz1, S.parPERC);
    const float suz2 = suz1 - perc;
    const float q0 = S.parK0 * fmaxf(suz2 - S.parUZL, 0.0f);
    const float suz3 = suz2 - q0;
    const float q1 = S.parK1 * suz3;
    suz = suz3 - q1;
    const float slzp = slz2 + perc;
    const float slza = fmaxf(slzp - S.gwcap, 0.0f);
    const float q2 = S.parK2 * slza;
    slz = slza - q2;
    const float qt = (q0 + q1) + q2;

    // --- routing: own component, 15 taps (weights pre-scaled by 0.5);
    //     flow = own partial + sibling partial (one shfl).
    float a0 = w[0] * qt;
    float a1 = w[5] * qh[(RP + 14 - 5) % 14];
    float a2 = w[10] * qh[(RP + 14 - 10) % 14];
    #pragma unroll
    for (int k = 1; k <= 4; ++k)  a0 = fmaf(w[k], qh[(RP + 14 - k) % 14], a0);
    #pragma unroll
    for (int k = 6; k <= 9; ++k)  a1 = fmaf(w[k], qh[(RP + 14 - k) % 14], a1);
    #pragma unroll
    for (int k = 11; k <= 14; ++k) a2 = fmaf(w[k], qh[(RP + 14 - k) % 14], a2);
    qh[RP] = qt;
    const float partial = (a0 + a1) + a2;
    const float flow = partial + __shfl_xor_sync(0xffffffffu, partial, 1);

    if (store_ok) outp[SL * N_GRID] = flow;
}

__global__ void __launch_bounds__(BLK) hbv_fused(
    const float* __restrict__ x_phy,   // [T, G, 3]
    const float* __restrict__ ac_all,  // [G]
    const float* __restrict__ pdy,     // [T, G, 2, 2]
    const float* __restrict__ pstat,   // [G, 30]
    float* __restrict__ out)           // [T, G]
{
    __shared__ Smem smem;

    const int gb  = blockIdx.x * GPB;
    const int lg  = threadIdx.x >> 1;
    const int m   = threadIdx.x & 1;
    const int g   = gb + lg;
    const bool store_ok = (g < N_GRID) && (m == 0);
    const int gc  = (g < N_GRID) ? g : (N_GRID - 1);
    const int c   = threadIdx.x;

    // ---------- static params ----------
    const float* ps = pstat + gc * 30;
    const float Ac = ac_all[gc];
    Chain S;
    S.parFC    = ps[0*2+m]  * 950.0f  + 50.0f;
    S.parK0    = ps[1*2+m]  * 0.85f   + 0.05f;
    S.parK1    = ps[2*2+m]  * 0.49f   + 0.01f;
    S.parK2    = ps[3*2+m]  * 0.199f  + 0.001f;
    const float parLP = ps[4*2+m] * 0.8f + 0.2f;
    S.parPERC  = ps[5*2+m]  * 10.0f;
    S.parUZL   = ps[6*2+m]  * 100.0f;
    S.parTT    = ps[7*2+m]  * 5.0f    - 2.5f;
    S.parCFMAX = ps[8*2+m]  * 9.5f    + 0.5f;
    const float parCFR = ps[9*2+m] * 0.1f;
    S.parCWH   = ps[10*2+m] * 0.2f;
    S.parC     = ps[11*2+m];
    const float parRT = ps[12*2+m] * 20.0f;
    const float parAC = ps[13*2+m] * 2500.0f;
    S.invFC   = 1.0f / S.parFC;
    S.invLPFC = 1.0f / (parLP * S.parFC);
    S.crf     = parCFR * S.parCFMAX;
    S.gwcap   = parRT * fminf(fmaxf(1.0f - Ac / (parAC + NEARZERO), 0.0f), 1.0f);
    S.cfmaxTT = S.parCFMAX * S.parTT;
    S.crfTT   = S.crf * S.parTT;

    // ---------- normalized gamma-UH weights (pre-scaled by 0.5) ----------
    const float a_r  = fmaxf(ps[28] * 2.9f, 0.0f) + 0.1f;
    const float th_r = fmaxf(ps[29] * 6.5f, 0.0f) + 0.5f;
    const float am1  = a_r - 1.0f;
    const float ivtl = 1.4426950408889634f / th_r;
    const float LOG2TK[LENF] = {
        -1.0f,        0.5849625f, 1.3219281f, 1.8073549f, 2.1699250f,
         2.4594316f,  2.7004397f, 2.9068906f, 3.0874628f, 3.2479275f,
         3.3923174f,  3.5235620f, 3.6438562f, 3.7548875f, 3.8579810f };
    float w[LENF];
    float wsum = 0.0f;
    #pragma unroll
    for (int k = 0; k < LENF; ++k) {
        const float tk = (float)k + 0.5f;
        w[k] = ex2a(am1 * LOG2TK[k] - tk * ivtl);
        wsum += w[k];
    }
    const float ivw = 0.5f / wsum;
    #pragma unroll
    for (int k = 0; k < LENF; ++k) w[k] *= ivw;

    // ---------- state ----------
    float snowpack = 1e-3f, meltwater = 1e-3f, sm = 1e-3f, suz = 1e-3f, slz = 1e-3f;
    float lsm = lg2a(1e-3f * S.invFC);
    float qh[14];
    #pragma unroll
    for (int k = 0; k < 14; ++k) qh[k] = 0.0f;

    // shared read base pointers
    const float* px0 = &smem.sx[0][0][lg * 3];
    const float* pda = &smem.sd[0][0][lg * 4 + m];
    const float* pdb = &smem.sd[0][0][lg * 4 + 2 + m];
    const int xstride = CHUNK * GPB * 3;
    const int dstride = CHUNK * GPB * 4;

    // ---------- pipeline prologue ----------
    stage(smem, 0, gb, x_phy, pdy, c);
    asm volatile("cp.async.commit_group;\n");
    stage(smem, 1, gb, x_phy, pdy, c);
    asm volatile("cp.async.commit_group;\n");

    // ---------- main loop: 52 chunk-pairs (104 chunks, t = 0..727) ----------
    #define STEPS7(B) \
        step_body<B+0>(S, snowpack, meltwater, sm, suz, slz, lsm, w, qh, px, p0, p1, store_ok, outp); \
        step_body<B+1>(S, snowpack, meltwater, sm, suz, slz, lsm, w, qh, px, p0, p1, store_ok, outp); \
        step_body<B+2>(S, snowpack, meltwater, sm, suz, slz, lsm, w, qh, px, p0, p1, store_ok, outp); \
        step_body<B+3>(S, snowpack, meltwater, sm, suz, slz, lsm, w, qh, px, p0, p1, store_ok, outp); \
        step_body<B+4>(S, snowpack, meltwater, sm, suz, slz, lsm, w, qh, px, p0, p1, store_ok, outp); \
        step_body<B+5>(S, snowpack, meltwater, sm, suz, slz, lsm, w, qh, px, p0, p1, store_ok, outp); \
        step_body<B+6>(S, snowpack, meltwater, sm, suz, slz, lsm, w, qh, px, p0, p1, store_ok, outp);

    for (int p = 0; p < 52; ++p) {
        // chunk 2p (buf 0, ring phase 0..6)
        {
            asm volatile("cp.async.wait_group 1;\n");
            __syncthreads();
            const float* px = px0;
            const float* p0 = pda;
            const float* p1 = pdb;
            float* outp = out + (2 * p) * (CHUNK * N_GRID) + g;
            STEPS7(0)
            __syncthreads();
            if (2 * p + 2 < NCHUNKS) stage(smem, 2 * p + 2, gb, x_phy, pdy, c);
            asm volatile("cp.async.commit_group;\n");
        }
        // chunk 2p+1 (buf 1, ring phase 7..13)
        {
            asm volatile("cp.async.wait_group 1;\n");
            __syncthreads();
            const float* px = px0 + xstride;
            const float* p0 = pda + dstride;
            const float* p1 = pdb + dstride;
            float* outp = out + (2 * p + 1) * (CHUNK * N_GRID) + g;
            STEPS7(7)
            __syncthreads();
            if (2 * p + 3 < NCHUNKS) stage(smem, 2 * p + 3, gb, x_phy, pdy, c);
            asm volatile("cp.async.commit_group;\n");
        }
    }

    // ---------- epilogue: chunk 104 (buf 0, ring phase 0), live steps 728..729 ----------
    asm volatile("cp.async.wait_group 0;\n");
    __syncthreads();
    {
        const float* px = px0;
        const float* p0 = pda;
        const float* p1 = pdb;
        float* outp = out + 104 * (CHUNK * N_GRID) + g;
        step_body<0>(S, snowpack, meltwater, sm, suz, slz, lsm, w, qh, px, p0, p1, store_ok, outp);
        step_body<1>(S, snowpack, meltwater, sm, suz, slz, lsm, w, qh, px, p0, p1, store_ok, outp);
    }
    #undef STEPS7
}

// ---------------------------------------------------------------------------
extern "C" void kernel_launch(void* const* d_in, const int* in_sizes, int n_in,
                              void* d_out, int out_size)
{
    const float* x_phy = (const float*)d_in[0];   // [730,10000,3]
    const float* ac    = (const float*)d_in[1];   // [10000]
    // d_in[2] = elev_all (unused)
    const float* pdy   = (const float*)d_in[3];   // [730,10000,4]
    const float* pstat = (const float*)d_in[4];   // [10000,30]
    float* out = (float*)d_out;                   // [730,10000,1]

    const int nblocks = (N_GRID + GPB - 1) / GPB;  // 105
    hbv_fused<<<nblocks, BLK>>>(x_phy, ac, pdy, pstat, out);
}

// round 10
// speedup vs baseline: 1.1842x; 1.1691x over previous
#include <cuda_runtime.h>

#define T_STEPS 730
#define N_GRID  10000
#define LENF    15
#define NEARZERO 1e-5f
#define BLK   128           // 4 warps; each warp owns 16 cells, fully independent
#define GPB   64            // grid cells per block
#define CPW   16            // cells per warp
#define CHUNK 7             // timesteps per stage
#define NCHUNKS 105         // ceil(730/7); chunk 104 has 2 live steps

// Shared staging: [buf][step][cell data]; each warp touches only its own slice.
struct __align__(16) Smem {
    float sx[2][CHUNK][GPB * 3];   // P, Ta, PET per cell
    float sd[2][CHUNK][GPB * 4];   // parBETA(m0,m1), parBETAET(m0,m1)
};

__device__ __forceinline__ void cp16(void* dst_smem, const void* src) {
    unsigned d = (unsigned)__cvta_generic_to_shared(dst_smem);
    asm volatile("cp.async.ca.shared.global [%0], [%1], 16;\n" :: "r"(d), "l"(src));
}
__device__ __forceinline__ float lg2a(float x) {
    float r; asm("lg2.approx.f32 %0, %1;" : "=f"(r) : "f"(x)); return r;
}
__device__ __forceinline__ float ex2a(float x) {
    float r; asm("ex2.approx.f32 %0, %1;" : "=f"(r) : "f"(x)); return r;
}

// Per-warp staging: warp w stages CHUNK steps of ITS OWN 16 cells into buf ch&1.
// x slice: 7 steps * 12 vecs = 84 vecs; d slice: 7 steps * 16 vecs = 112 vecs.
__device__ __forceinline__ void stage(
    Smem& s, int ch, int gb, int w, int lane,
    const float* __restrict__ x_phy, const float* __restrict__ pdy)
{
    const int buf = ch & 1;
    const int t0  = ch * CHUNK;
    const int limx = T_STEPS * N_GRID * 3 - 4;
    #pragma unroll
    for (int v = 0; v < 3; ++v) {
        const int i = lane + v * 32;
        if (i < CHUNK * 12) {                       // 84
            const int st = i / 12, o = i % 12;
            int idx = (t0 + st) * (N_GRID * 3) + gb * 3 + w * 48 + o * 4;
            idx = (idx > limx) ? limx : idx;
            cp16(&s.sx[buf][st][w * 48 + o * 4], x_phy + idx);
        }
    }
    const int limd = T_STEPS * N_GRID * 4 - 4;
    #pragma unroll
    for (int v = 0; v < 4; ++v) {
        const int i = lane + v * 32;
        if (i < CHUNK * 16) {                       // 112
            const int st = i >> 4, o = i & 15;
            int idx = (t0 + st) * (N_GRID * 4) + gb * 4 + w * 64 + o * 4;
            idx = (idx > limd) ? limd : idx;
            cp16(&s.sd[buf][st][w * 64 + o * 4], pdy + idx);
        }
    }
}

// Per-component HBV parameters (hoisted/precombined)
struct Chain {
    float parFC, parK0, parK1, parK2, parPERC, parUZL, parTT,
          parCFMAX, parCWH, parC;
    float invFC, invLPFC, crf, gwcap, cfmaxTT, crfTT;
};

// One HBV step + per-component 15-tap routing (weights pre-scaled by 0.5).
// RP = t mod 14 (compile-time): static ring indexing. Slot in buffer = RP%7.
template<int RP>
__device__ __forceinline__ void step_body(
    const Chain& S, float& snowpack, float& meltwater, float& sm, float& suz,
    float& slz, float& lsm,
    const float (&w)[LENF], float (&qh)[14],
    const float* __restrict__ px, const float* __restrict__ pd0,
    const float* __restrict__ pd1,
    bool store_ok, float* __restrict__ outp)
{
    constexpr int SL = RP % 7;
    const float P  = px[SL * (GPB * 3) + 0];
    const float Ta = px[SL * (GPB * 3) + 1];
    const float PE = px[SL * (GPB * 3) + 2];
    const float beta   = pd0[SL * (GPB * 4)] * 5.0f + 1.0f;   // [1,6]
    const float betaet = pd1[SL * (GPB * 4)] * 4.7f + 0.3f;   // [0.3,5]

    // swet from carried lsm = lg2(sm_prev * invFC)
    const float swet = __saturatef(ex2a(beta * lsm));

    // --- snow bucket ---
    const bool wet = (Ta >= S.parTT);
    const float rain = wet ? P : 0.0f;
    const float snow = wet ? 0.0f : P;
    const float melt0 = fmaxf(fmaf(S.parCFMAX, Ta, -S.cfmaxTT), 0.0f);
    const float refr0 = fmaxf(fmaf(-S.crf, Ta, S.crfTT), 0.0f);
    float sp1 = snowpack + snow;
    const float melt = fminf(melt0, sp1);
    float mw1 = meltwater + melt;
    sp1 -= melt;
    const float refr = fminf(refr0, mw1);
    sp1 += refr;
    mw1 -= refr;
    const float tosoil = fmaxf(fmaf(-S.parCWH, sp1, mw1), 0.0f);
    snowpack = sp1;
    meltwater = mw1 - tosoil;

    // --- soil bucket ---
    const float rpt = rain + tosoil;
    const float recharge = rpt * swet;
    const float sm1 = sm + (rpt - recharge);
    const float sm2 = fminf(sm1, S.parFC);
    const float excess = sm1 - sm2;
    const float efb = __saturatef(sm2 * S.invLPFC);
    const float ef  = ex2a(betaet * lg2a(efb));
    const float sm3 = fmaxf(fmaf(-PE, ef, sm2), NEARZERO);
    const float cslz = S.parC * slz;
    const float f1  = 1.0f - __saturatef(sm3 * S.invFC);
    const float cap = fminf(cslz * f1, slz);
    const float sm4 = fmaxf(sm3 + cap, NEARZERO);
    float slz2 = fmaxf(slz - cap, NEARZERO);
    sm = sm4;
    lsm = lg2a(sm4 * S.invFC);          // tail: feeds next step's swet

    // --- groundwater buckets ---
    const float suz1 = suz + (recharge + excess);
    const float perc = fminf(suz1, S.parPERC);
    const float suz2 = suz1 - perc;
    const float q0 = S.parK0 * fmaxf(suz2 - S.parUZL, 0.0f);
    const float suz3 = suz2 - q0;
    const float q1 = S.parK1 * suz3;
    suz = suz3 - q1;
    const float slzp = slz2 + perc;
    const float slza = fmaxf(slzp - S.gwcap, 0.0f);
    const float q2 = S.parK2 * slza;
    slz = slza - q2;
    const float qt = (q0 + q1) + q2;

    // --- routing: own component, 15 taps (weights pre-scaled by 0.5);
    //     flow = own partial + sibling partial (one shfl).
    float a0 = w[0] * qt;
    float a1 = w[5] * qh[(RP + 14 - 5) % 14];
    float a2 = w[10] * qh[(RP + 14 - 10) % 14];
    #pragma unroll
    for (int k = 1; k <= 4; ++k)  a0 = fmaf(w[k], qh[(RP + 14 - k) % 14], a0);
    #pragma unroll
    for (int k = 6; k <= 9; ++k)  a1 = fmaf(w[k], qh[(RP + 14 - k) % 14], a1);
    #pragma unroll
    for (int k = 11; k <= 14; ++k) a2 = fmaf(w[k], qh[(RP + 14 - k) % 14], a2);
    qh[RP] = qt;
    const float partial = (a0 + a1) + a2;
    const float flow = partial + __shfl_xor_sync(0xffffffffu, partial, 1);

    if (store_ok) outp[SL * N_GRID] = flow;
}

__global__ void __launch_bounds__(BLK) hbv_fused(
    const float* __restrict__ x_phy,   // [T, G, 3]
    const float* __restrict__ ac_all,  // [G]
    const float* __restrict__ pdy,     // [T, G, 2, 2]
    const float* __restrict__ pstat,   // [G, 30]
    float* __restrict__ out)           // [T, G]
{
    __shared__ Smem smem;

    const int gb   = blockIdx.x * GPB;
    const int wrp  = threadIdx.x >> 5;       // warp in block: owns cells gb+wrp*16 ..+15
    const int lane = threadIdx.x & 31;
    const int lg   = threadIdx.x >> 1;       // cell within block
    const int m    = threadIdx.x & 1;
    const int g    = gb + lg;

    // Whole-warp early exit: 10000 % 16 == 0, so a warp is either fully live
    // or fully dead. No block barriers exist, so this is safe.
    if (gb + wrp * CPW >= N_GRID) return;
    const bool store_ok = (m == 0);           // all remaining cells are valid

    // ---------- static params ----------
    const float* ps = pstat + g * 30;
    const float Ac = ac_all[g];
    Chain S;
    S.parFC    = ps[0*2+m]  * 950.0f  + 50.0f;
    S.parK0    = ps[1*2+m]  * 0.85f   + 0.05f;
    S.parK1    = ps[2*2+m]  * 0.49f   + 0.01f;
    S.parK2    = ps[3*2+m]  * 0.199f  + 0.001f;
    const float parLP = ps[4*2+m] * 0.8f + 0.2f;
    S.parPERC  = ps[5*2+m]  * 10.0f;
    S.parUZL   = ps[6*2+m]  * 100.0f;
    S.parTT    = ps[7*2+m]  * 5.0f    - 2.5f;
    S.parCFMAX = ps[8*2+m]  * 9.5f    + 0.5f;
    const float parCFR = ps[9*2+m] * 0.1f;
    S.parCWH   = ps[10*2+m] * 0.2f;
    S.parC     = ps[11*2+m];
    const float parRT = ps[12*2+m] * 20.0f;
    const float parAC = ps[13*2+m] * 2500.0f;
    S.invFC   = 1.0f / S.parFC;
    S.invLPFC = 1.0f / (parLP * S.parFC);
    S.crf     = parCFR * S.parCFMAX;
    S.gwcap   = parRT * fminf(fmaxf(1.0f - Ac / (parAC + NEARZERO), 0.0f), 1.0f);
    S.cfmaxTT = S.parCFMAX * S.parTT;
    S.crfTT   = S.crf * S.parTT;

    // ---------- normalized gamma-UH weights (pre-scaled by 0.5) ----------
    const float a_r  = fmaxf(ps[28] * 2.9f, 0.0f) + 0.1f;
    const float th_r = fmaxf(ps[29] * 6.5f, 0.0f) + 0.5f;
    const float am1  = a_r - 1.0f;
    const float ivtl = 1.4426950408889634f / th_r;
    const float LOG2TK[LENF] = {
        -1.0f,        0.5849625f, 1.3219281f, 1.8073549f, 2.1699250f,
         2.4594316f,  2.7004397f, 2.9068906f, 3.0874628f, 3.2479275f,
         3.3923174f,  3.5235620f, 3.6438562f, 3.7548875f, 3.8579810f };
    float w[LENF];
    float wsum = 0.0f;
    #pragma unroll
    for (int k = 0; k < LENF; ++k) {
        const float tk = (float)k + 0.5f;
        w[k] = ex2a(am1 * LOG2TK[k] - tk * ivtl);
        wsum += w[k];
    }
    const float ivw = 0.5f / wsum;
    #pragma unroll
    for (int k = 0; k < LENF; ++k) w[k] *= ivw;

    // ---------- state ----------
    float snowpack = 1e-3f, meltwater = 1e-3f, sm = 1e-3f, suz = 1e-3f, slz = 1e-3f;
    float lsm = lg2a(1e-3f * S.invFC);
    float qh[14];
    #pragma unroll
    for (int k = 0; k < 14; ++k) qh[k] = 0.0f;

    // shared read base pointers
    const float* px0 = &smem.sx[0][0][lg * 3];
    const float* pda = &smem.sd[0][0][lg * 4 + m];
    const float* pdb = &smem.sd[0][0][lg * 4 + 2 + m];
    const int xstride = CHUNK * GPB * 3;
    const int dstride = CHUNK * GPB * 4;

    // ---------- per-warp pipeline prologue ----------
    stage(smem, 0, gb, wrp, lane, x_phy, pdy);
    asm volatile("cp.async.commit_group;\n");
    stage(smem, 1, gb, wrp, lane, x_phy, pdy);
    asm volatile("cp.async.commit_group;\n");

    // ---------- main loop: 52 chunk-pairs (104 chunks, t = 0..727) ----------
    #define STEPS7(B) \
        step_body<B+0>(S, snowpack, meltwater, sm, suz, slz, lsm, w, qh, px, p0, p1, store_ok, outp); \
        step_body<B+1>(S, snowpack, meltwater, sm, suz, slz, lsm, w, qh, px, p0, p1, store_ok, outp); \
        step_body<B+2>(S, snowpack, meltwater, sm, suz, slz, lsm, w, qh, px, p0, p1, store_ok, outp); \
        step_body<B+3>(S, snowpack, meltwater, sm, suz, slz, lsm, w, qh, px, p0, p1, store_ok, outp); \
        step_body<B+4>(S, snowpack, meltwater, sm, suz, slz, lsm, w, qh, px, p0, p1, store_ok, outp); \
        step_body<B+5>(S, snowpack, meltwater, sm, suz, slz, lsm, w, qh, px, p0, p1, store_ok, outp); \
        step_body<B+6>(S, snowpack, meltwater, sm, suz, slz, lsm, w, qh, px, p0, p1, store_ok, outp);

    for (int p = 0; p < 52; ++p) {
        // chunk 2p (buf 0, ring phase 0..6)
        {
            asm volatile("cp.async.wait_group 1;\n");
            __syncwarp();
            const float* px = px0;
            const float* p0 = pda;
            const float* p1 = pdb;
            float* outp = out + (2 * p) * (CHUNK * N_GRID) + g;
            STEPS7(0)
            if (2 * p + 2 < NCHUNKS) stage(smem, 2 * p + 2, gb, wrp, lane, x_phy, pdy);
            asm volatile("cp.async.commit_group;\n");
        }
        // chunk 2p+1 (buf 1, ring phase 7..13)
        {
            asm volatile("cp.async.wait_group 1;\n");
            __syncwarp();
            const float* px = px0 + xstride;
            const float* p0 = pda + dstride;
            const float* p1 = pdb + dstride;
            float* outp = out + (2 * p + 1) * (CHUNK * N_GRID) + g;
            STEPS7(7)
            if (2 * p + 3 < NCHUNKS) stage(smem, 2 * p + 3, gb, wrp, lane, x_phy, pdy);
            asm volatile("cp.async.commit_group;\n");
        }
    }

    // ---------- epilogue: chunk 104 (buf 0, ring phase 0), live steps 728..729 ----------
    asm volatile("cp.async.wait_group 0;\n");
    __syncwarp();
    {
        const float* px = px0;
        const float* p0 = pda;
        const float* p1 = pdb;
        float* outp = out + 104 * (CHUNK * N_GRID) + g;
        step_body<0>(S, snowpack, meltwater, sm, suz, slz, lsm, w, qh, px, p0, p1, store_ok, outp);
        step_body<1>(S, snowpack, meltwater, sm, suz, slz, lsm, w, qh, px, p0, p1, store_ok, outp);
    }
    #undef STEPS7
}

// ---------------------------------------------------------------------------
extern "C" void kernel_launch(void* const* d_in, const int* in_sizes, int n_in,
                              void* d_out, int out_size)
{
    const float* x_phy = (const float*)d_in[0];   // [730,10000,3]
    const float* ac    = (const float*)d_in[1];   // [10000]
    // d_in[2] = elev_all (unused)
    const float* pdy   = (const float*)d_in[3];   // [730,10000,4]
    const float* pstat = (const float*)d_in[4];   // [10000,30]
    float* out = (float*)d_out;                   // [730,10000,1]

    hbv_fused<<<(2 * N_GRID + BLK - 1) / BLK, BLK>>>(x_phy, ac, pdy, pstat, out);
}

// round 11
// speedup vs baseline: 1.2776x; 1.0788x over previous
#include <cuda_runtime.h>

#define T_STEPS 730
#define N_GRID  10000
#define LENF    15
#define NEARZERO 1e-5f
#define BLK   128           // 4 warps; each warp owns 16 cells, fully independent
#define GPB   64            // grid cells per block
#define CPW   16            // cells per warp
#define CHUNK 7             // timesteps per stage
#define NCHUNKS 105         // ceil(730/7); chunk 104 has 2 live steps

// Shared staging: [buf][step][cell data]; each warp touches only its own slice.
struct __align__(16) Smem {
    float sx[2][CHUNK][GPB * 3];   // P, Ta, PET per cell
    float sd[2][CHUNK][GPB * 4];   // parBETA(m0,m1), parBETAET(m0,m1)
};

__device__ __forceinline__ void cp16(void* dst_smem, const void* src) {
    unsigned d = (unsigned)__cvta_generic_to_shared(dst_smem);
    asm volatile("cp.async.ca.shared.global [%0], [%1], 16;\n" :: "r"(d), "l"(src));
}
__device__ __forceinline__ float lg2a(float x) {
    float r; asm("lg2.approx.f32 %0, %1;" : "=f"(r) : "f"(x)); return r;
}
__device__ __forceinline__ float ex2a(float x) {
    float r; asm("ex2.approx.f32 %0, %1;" : "=f"(r) : "f"(x)); return r;
}

// Per-warp staging: warp w stages CHUNK steps of ITS OWN 16 cells into buf ch&1.
// x slice: 7 steps * 12 vecs = 84 vecs; d slice: 7 steps * 16 vecs = 112 vecs.
__device__ __forceinline__ void stage(
    Smem& s, int ch, int gb, int w, int lane,
    const float* __restrict__ x_phy, const float* __restrict__ pdy)
{
    const int buf = ch & 1;
    const int t0  = ch * CHUNK;
    const int limx = T_STEPS * N_GRID * 3 - 4;
    #pragma unroll
    for (int v = 0; v < 3; ++v) {
        const int i = lane + v * 32;
        if (i < CHUNK * 12) {                       // 84
            const int st = i / 12, o = i % 12;
            int idx = (t0 + st) * (N_GRID * 3) + gb * 3 + w * 48 + o * 4;
            idx = (idx > limx) ? limx : idx;
            cp16(&s.sx[buf][st][w * 48 + o * 4], x_phy + idx);
        }
    }
    const int limd = T_STEPS * N_GRID * 4 - 4;
    #pragma unroll
    for (int v = 0; v < 4; ++v) {
        const int i = lane + v * 32;
        if (i < CHUNK * 16) {                       // 112
            const int st = i >> 4, o = i & 15;
            int idx = (t0 + st) * (N_GRID * 4) + gb * 4 + w * 64 + o * 4;
            idx = (idx > limd) ? limd : idx;
            cp16(&s.sd[buf][st][w * 64 + o * 4], pdy + idx);
        }
    }
}

// Per-component HBV parameters (hoisted/precombined)
struct Chain {
    float parFC, parK0, parK1, parK2, parPERC, parUZL, parTT,
          parCFMAX, parCWH, parC;
    float invFC, invLPFC, crf, gwcap, cfmaxTT, crfTT;
};

// One HBV step + per-component 15-tap routing (weights pre-scaled by 0.5).
// RP = t mod 14 (compile-time): static ring indexing. Slot in buffer = RP%7.
template<int RP>
__device__ __forceinline__ void step_body(
    const Chain& S, float& snowpack, float& meltwater, float& sm, float& suz,
    float& slz, float& lsm,
    const float (&w)[LENF], float (&qh)[14], int m,
    const float* __restrict__ px, const float* __restrict__ pd,
    bool store_ok, float* __restrict__ outp)
{
    constexpr int SL = RP % 7;
    const float P  = px[SL * (GPB * 3) + 0];
    const float Ta = px[SL * (GPB * 3) + 1];
    const float PE = px[SL * (GPB * 3) + 2];
    // one LDS.128 for all 4 dynamic params of this cell; select by component
    const float4 dv = *reinterpret_cast<const float4*>(pd + SL * (GPB * 4));
    const float beta   = (m ? dv.y : dv.x) * 5.0f + 1.0f;   // [1,6]
    const float betaet = (m ? dv.w : dv.z) * 4.7f + 0.3f;   // [0.3,5]

    // swet from carried lsm = lg2(sm_prev * invFC)
    const float swet = __saturatef(ex2a(beta * lsm));

    // --- snow bucket ---
    const bool wet = (Ta >= S.parTT);
    const float rain = wet ? P : 0.0f;
    const float snow = wet ? 0.0f : P;
    const float melt0 = fmaxf(fmaf(S.parCFMAX, Ta, -S.cfmaxTT), 0.0f);
    const float refr0 = fmaxf(fmaf(-S.crf, Ta, S.crfTT), 0.0f);
    float sp1 = snowpack + snow;
    const float melt = fminf(melt0, sp1);
    float mw1 = meltwater + melt;
    sp1 -= melt;
    const float refr = fminf(refr0, mw1);
    sp1 += refr;
    mw1 -= refr;
    const float tosoil = fmaxf(fmaf(-S.parCWH, sp1, mw1), 0.0f);
    snowpack = sp1;
    meltwater = mw1 - tosoil;

    // --- soil bucket ---
    const float rpt = rain + tosoil;
    const float recharge = rpt * swet;                 // off-chain (feeds suz)
    const float sm1 = fmaf(-rpt, swet, sm + rpt);      // == sm + rpt - recharge
    const float sm2 = fminf(sm1, S.parFC);
    const float excess = sm1 - sm2;
    const float efb = __saturatef(sm2 * S.invLPFC);
    const float ef  = ex2a(betaet * lg2a(efb));
    const float sm3 = fmaxf(fmaf(-PE, ef, sm2), NEARZERO);
    const float cslz = S.parC * slz;                   // off-chain
    const float s3  = __saturatef(sm3 * S.invFC);
    const float cap = fminf(fmaf(-cslz, s3, cslz), slz);   // == min(cslz*(1-s3), slz)
    const float sm4 = fmaxf(sm3 + cap, NEARZERO);
    float slz2 = fmaxf(slz - cap, NEARZERO);
    sm = sm4;
    lsm = lg2a(sm4 * S.invFC);          // tail: feeds next step's swet

    // --- groundwater buckets ---
    const float suz1 = suz + (recharge + excess);
    const float perc = fminf(suz1, S.parPERC);
    const float suz2 = suz1 - perc;
    const float q0 = S.parK0 * fmaxf(suz2 - S.parUZL, 0.0f);
    const float suz3 = suz2 - q0;
    const float q1 = S.parK1 * suz3;
    suz = suz3 - q1;
    const float slzp = slz2 + perc;
    const float slza = fmaxf(slzp - S.gwcap, 0.0f);
    const float q2 = S.parK2 * slza;
    slz = slza - q2;
    const float qt = (q0 + q1) + q2;

    // --- routing: own component, 15 taps (weights pre-scaled by 0.5);
    //     flow = own partial + sibling partial (one shfl).
    float a0 = w[0] * qt;
    float a1 = w[5] * qh[(RP + 14 - 5) % 14];
    float a2 = w[10] * qh[(RP + 14 - 10) % 14];
    #pragma unroll
    for (int k = 1; k <= 4; ++k)  a0 = fmaf(w[k], qh[(RP + 14 - k) % 14], a0);
    #pragma unroll
    for (int k = 6; k <= 9; ++k)  a1 = fmaf(w[k], qh[(RP + 14 - k) % 14], a1);
    #pragma unroll
    for (int k = 11; k <= 14; ++k) a2 = fmaf(w[k], qh[(RP + 14 - k) % 14], a2);
    qh[RP] = qt;
    const float partial = (a0 + a1) + a2;
    const float flow = partial + __shfl_xor_sync(0xffffffffu, partial, 1);

    if (store_ok) outp[SL * N_GRID] = flow;
}

__global__ void __launch_bounds__(BLK, 1) hbv_fused(
    const float* __restrict__ x_phy,   // [T, G, 3]
    const float* __restrict__ ac_all,  // [G]
    const float* __restrict__ pdy,     // [T, G, 2, 2]
    const float* __restrict__ pstat,   // [G, 30]
    float* __restrict__ out)           // [T, G]
{
    __shared__ Smem smem;

    const int gb   = blockIdx.x * GPB;
    const int wrp  = threadIdx.x >> 5;       // warp in block: owns cells gb+wrp*16 ..+15
    const int lane = threadIdx.x & 31;
    const int lg   = threadIdx.x >> 1;       // cell within block
    const int m    = threadIdx.x & 1;
    const int g    = gb + lg;

    // Whole-warp early exit: 10000 % 16 == 0, so a warp is either fully live
    // or fully dead. No block barriers exist, so this is safe.
    if (gb + wrp * CPW >= N_GRID) return;
    const bool store_ok = (m == 0);

    // ---------- static params ----------
    const float* ps = pstat + g * 30;
    const float Ac = ac_all[g];
    Chain S;
    S.parFC    = ps[0*2+m]  * 950.0f  + 50.0f;
    S.parK0    = ps[1*2+m]  * 0.85f   + 0.05f;
    S.parK1    = ps[2*2+m]  * 0.49f   + 0.01f;
    S.parK2    = ps[3*2+m]  * 0.199f  + 0.001f;
    const float parLP = ps[4*2+m] * 0.8f + 0.2f;
    S.parPERC  = ps[5*2+m]  * 10.0f;
    S.parUZL   = ps[6*2+m]  * 100.0f;
    S.parTT    = ps[7*2+m]  * 5.0f    - 2.5f;
    S.parCFMAX = ps[8*2+m]  * 9.5f    + 0.5f;
    const float parCFR = ps[9*2+m] * 0.1f;
    S.parCWH   = ps[10*2+m] * 0.2f;
    S.parC     = ps[11*2+m];
    const float parRT = ps[12*2+m] * 20.0f;
    const float parAC = ps[13*2+m] * 2500.0f;
    S.invFC   = 1.0f / S.parFC;
    S.invLPFC = 1.0f / (parLP * S.parFC);
    S.crf     = parCFR * S.parCFMAX;
    S.gwcap   = parRT * fminf(fmaxf(1.0f - Ac / (parAC + NEARZERO), 0.0f), 1.0f);
    S.cfmaxTT = S.parCFMAX * S.parTT;
    S.crfTT   = S.crf * S.parTT;

    // ---------- normalized gamma-UH weights (pre-scaled by 0.5) ----------
    const float a_r  = fmaxf(ps[28] * 2.9f, 0.0f) + 0.1f;
    const float th_r = fmaxf(ps[29] * 6.5f, 0.0f) + 0.5f;
    const float am1  = a_r - 1.0f;
    const float ivtl = 1.4426950408889634f / th_r;
    const float LOG2TK[LENF] = {
        -1.0f,        0.5849625f, 1.3219281f, 1.8073549f, 2.1699250f,
         2.4594316f,  2.7004397f, 2.9068906f, 3.0874628f, 3.2479275f,
         3.3923174f,  3.5235620f, 3.6438562f, 3.7548875f, 3.8579810f };
    float w[LENF];
    float wsum = 0.0f;
    #pragma unroll
    for (int k = 0; k < LENF; ++k) {
        const float tk = (float)k + 0.5f;
        w[k] = ex2a(am1 * LOG2TK[k] - tk * ivtl);
        wsum += w[k];
    }
    const float ivw = 0.5f / wsum;
    #pragma unroll
    for (int k = 0; k < LENF; ++k) w[k] *= ivw;

    // ---------- state ----------
    float snowpack = 1e-3f, meltwater = 1e-3f, sm = 1e-3f, suz = 1e-3f, slz = 1e-3f;
    float lsm = lg2a(1e-3f * S.invFC);
    float qh[14];
    #pragma unroll
    for (int k = 0; k < 14; ++k) qh[k] = 0.0f;

    // shared read base pointers
    const float* px0 = &smem.sx[0][0][lg * 3];
    const float* pd0 = &smem.sd[0][0][lg * 4];
    const int xstride = CHUNK * GPB * 3;
    const int dstride = CHUNK * GPB * 4;

    // ---------- per-warp pipeline prologue ----------
    stage(smem, 0, gb, wrp, lane, x_phy, pdy);
    asm volatile("cp.async.commit_group;\n");
    stage(smem, 1, gb, wrp, lane, x_phy, pdy);
    asm volatile("cp.async.commit_group;\n");

    // ---------- main loop: 52 chunk-pairs (104 chunks, t = 0..727) ----------
    #define STEPS7(B) \
        step_body<B+0>(S, snowpack, meltwater, sm, suz, slz, lsm, w, qh, m, px, pd, store_ok, outp); \
        step_body<B+1>(S, snowpack, meltwater, sm, suz, slz, lsm, w, qh, m, px, pd, store_ok, outp); \
        step_body<B+2>(S, snowpack, meltwater, sm, suz, slz, lsm, w, qh, m, px, pd, store_ok, outp); \
        step_body<B+3>(S, snowpack, meltwater, sm, suz, slz, lsm, w, qh, m, px, pd, store_ok, outp); \
        step_body<B+4>(S, snowpack, meltwater, sm, suz, slz, lsm, w, qh, m, px, pd, store_ok, outp); \
        step_body<B+5>(S, snowpack, meltwater, sm, suz, slz, lsm, w, qh, m, px, pd, store_ok, outp); \
        step_body<B+6>(S, snowpack, meltwater, sm, suz, slz, lsm, w, qh, m, px, pd, store_ok, outp);

    for (int p = 0; p < 52; ++p) {
        // chunk 2p (buf 0, ring phase 0..6)
        {
            asm volatile("cp.async.wait_group 1;\n");
            __syncwarp();
            const float* px = px0;
            const float* pd = pd0;
            float* outp = out + (2 * p) * (CHUNK * N_GRID) + g;
            STEPS7(0)
            if (2 * p + 2 < NCHUNKS) stage(smem, 2 * p + 2, gb, wrp, lane, x_phy, pdy);
            asm volatile("cp.async.commit_group;\n");
        }
        // chunk 2p+1 (buf 1, ring phase 7..13)
        {
            asm volatile("cp.async.wait_group 1;\n");
            __syncwarp();
            const float* px = px0 + xstride;
            const float* pd = pd0 + dstride;
            float* outp = out + (2 * p + 1) * (CHUNK * N_GRID) + g;
            STEPS7(7)
            if (2 * p + 3 < NCHUNKS) stage(smem, 2 * p + 3, gb, wrp, lane, x_phy, pdy);
            asm volatile("cp.async.commit_group;\n");
        }
    }

    // ---------- epilogue: chunk 104 (buf 0, ring phase 0), live steps 728..729 ----------
    asm volatile("cp.async.wait_group 0;\n");
    __syncwarp();
    {
        const float* px = px0;
        const float* pd = pd0;
        float* outp = out + 104 * (CHUNK * N_GRID) + g;
        step_body<0>(S, snowpack, meltwater, sm, suz, slz, lsm, w, qh, m, px, pd, store_ok, outp);
        step_body<1>(S, snowpack, meltwater, sm, suz, slz, lsm, w, qh, m, px, pd, store_ok, outp);
    }
    #undef STEPS7
}

// ---------------------------------------------------------------------------
extern "C" void kernel_launch(void* const* d_in, const int* in_sizes, int n_in,
                              void* d_out, int out_size)
{
    const float* x_phy = (const float*)d_in[0];   // [730,10000,3]
    const float* ac    = (const float*)d_in[1];   // [10000]
    // d_in[2] = elev_all (unused)
    const float* pdy   = (const float*)d_in[3];   // [730,10000,4]
    const float* pstat = (const float*)d_in[4];   // [10000,30]
    float* out = (float*)d_out;                   // [730,10000,1]

    hbv_fused<<<(2 * N_GRID + BLK - 1) / BLK, BLK>>>(x_phy, ac, pdy, pstat, out);
}